// round 12
// baseline (speedup 1.0000x reference)
#include <cuda_runtime.h>

#define BATCH 4
#define CHN   1029
#define HH    80
#define WW    80
#define PLANE (HH * WW)
#define NROI  1024
#define PH    7
#define PW    7
#define SCALE 0.0625f
#define SP    81          // padded SAT row stride (odd -> conflict-free LDS)
#define SEG   20          // 4 segments of 20 cover 80
#define NSEG  4
#define NT    320         // 4*80 threads
#define CAP   640         // per-batch roi list capacity (mean 256, sd ~14)

// Single fused kernel: one block per (b,c) plane.
//   - Geometry for all 1024 rois computed per block (coalesced, L2-hot),
//     compacted to smem lists for batch b. Hidden inside Phase A's syncs.
//   - Segmented register-resident SAT build (validated config).
//   - Pooling: 4 SAT LDS + 1 store per bin over this batch's rois only.
__global__ __launch_bounds__(NT, 5) void psroi_fused_kernel(
    const float* __restrict__ in,       // (4,1029,80,80)
    const float* __restrict__ rois,     // (1024,5)
    float* __restrict__ out) {          // (1024,21,7,7) == (1024,1029)

    __shared__ float  s[SP][SP];        // padded SAT (26,244 B)
    __shared__ float  aux[NSEG][80];    // segment totals (reused by both scans)
    __shared__ float4 geo[CAP];         // x=sw, y=sh, z=bin_w, w=bin_h
    __shared__ int    idx[CAP];         // original roi index
    __shared__ int    cnt;

    const int tid   = threadIdx.x;
    const int plane = blockIdx.x;       // b*CHN + c
    const int b     = plane / CHN;
    const int c     = plane - b * CHN;

    if (tid == 0) cnt = 0;
    // zero pad row / pad col of the SAT
    if (tid < SP) s[0][tid] = 0.0f;
    else if (tid < SP + HH) s[tid - SP + 1][0] = 0.0f;

    const int seg  = tid / 80;          // 0..3
    const int lane = tid - seg * 80;    // 0..79

    // ---- Phase A part 1: load 20-elem column segment, cumsum in regs ----
    float v[SEG];
    {
        const float* __restrict__ col =
            in + (size_t)plane * PLANE + (size_t)(seg * SEG) * WW + lane;
        #pragma unroll
        for (int i = 0; i < SEG; ++i) v[i] = col[i * WW];   // 20 loads in flight
        #pragma unroll
        for (int i = 1; i < SEG; ++i) v[i] = __fadd_rn(v[i], v[i - 1]);
        aux[seg][lane] = v[SEG - 1];
    }
    __syncthreads();   // publishes aux AND cnt=0

    // ---- Phase A part 2: apply segment prefix, store to SAT ----
    {
        float p = 0.0f;
        #pragma unroll
        for (int j = 0; j < NSEG - 1; ++j)
            if (j < seg) p = __fadd_rn(p, aux[j][lane]);
        #pragma unroll
        for (int i = 0; i < SEG; ++i)
            s[seg * SEG + i + 1][lane + 1] = __fadd_rn(v[i], p);
    }

    // ---- Geometry + compaction (overlaps Phase A STS; validated numerics) ----
    {
        const float inv7 = 1.0f / 7.0f;   // correctly-rounded (XLA div->recip)
        for (int n = tid; n < NROI; n += NT) {
            const float r0 = rois[n * 5 + 0];
            if ((int)r0 != b) continue;
            const float r1 = rois[n * 5 + 1];
            const float r2 = rois[n * 5 + 2];
            const float r3 = rois[n * 5 + 3];
            const float r4 = rois[n * 5 + 4];

            const float roi_sw = __fmul_rn(floorf(__fadd_rn(r1, 0.5f)), SCALE);
            const float roi_sh = __fmul_rn(floorf(__fadd_rn(r2, 0.5f)), SCALE);
            const float roi_ew = __fmul_rn(floorf(__fadd_rn(__fadd_rn(r3, 1.0f), 0.5f)), SCALE);
            const float roi_eh = __fmul_rn(floorf(__fadd_rn(__fadd_rn(r4, 1.0f), 0.5f)), SCALE);

            const float roi_w = fmaxf(__fadd_rn(roi_ew, -roi_sw), 0.1f);
            const float roi_h = fmaxf(__fadd_rn(roi_eh, -roi_sh), 0.1f);
            const float bin_w = __fmul_rn(roi_w, inv7);
            const float bin_h = __fmul_rn(roi_h, inv7);

            const int slot = atomicAdd(&cnt, 1);
            if (slot < CAP) {
                geo[slot] = make_float4(roi_sw, roi_sh, bin_w, bin_h);
                idx[slot] = n;
            }
        }
    }
    __syncthreads();

    // ---- Phase B: W-cumsum, thread = (w-segment, row) ----
    {
        float* __restrict__ row = &s[lane + 1][seg * SEG + 1];
        float u[SEG];
        #pragma unroll
        for (int i = 0; i < SEG; ++i) u[i] = row[i];        // independent LDS
        #pragma unroll
        for (int i = 1; i < SEG; ++i) u[i] = __fadd_rn(u[i], u[i - 1]);

        aux[seg][lane] = u[SEG - 1];
        __syncthreads();

        float p = 0.0f;
        #pragma unroll
        for (int j = 0; j < NSEG - 1; ++j)
            if (j < seg) p = __fadd_rn(p, aux[j][lane]);

        #pragma unroll
        for (int i = 0; i < SEG; ++i)
            row[i] = __fadd_rn(u[i], p);
    }
    __syncthreads();

    // ---- Phase C: pooling, fixed (ph, pw); this batch's rois from smem ----
    const int k  = c % (PH * PW);
    const int ph = k / PW;
    const int pw = k - ph * PW;
    const float fph0 = (float)ph, fph1 = (float)(ph + 1);
    const float fpw0 = (float)pw, fpw1 = (float)(pw + 1);

    const int m = (cnt < CAP) ? cnt : CAP;
    for (int i = tid; i < m; i += NT) {
        const float4 gm = geo[i];
        const int    n  = idx[i];

        // Uncontracted rn mul+add edges (validated).
        const float hsf = floorf(__fadd_rn(__fmul_rn(fph0, gm.w), gm.y));
        const float hef = ceilf (__fadd_rn(__fmul_rn(fph1, gm.w), gm.y));
        const float wsf = floorf(__fadd_rn(__fmul_rn(fpw0, gm.z), gm.x));
        const float wef = ceilf (__fadd_rn(__fmul_rn(fpw1, gm.z), gm.x));

        const int hs = (int)fminf(fmaxf(hsf, 0.0f), (float)HH);
        const int he = (int)fminf(fmaxf(hef, 0.0f), (float)HH);
        const int ws = (int)fminf(fmaxf(wsf, 0.0f), (float)WW);
        const int we = (int)fminf(fmaxf(wef, 0.0f), (float)WW);

        const int area = (he - hs) * (we - ws);
        float res = 0.0f;
        if (area > 0) {
            const float ssum = __fadd_rn(__fadd_rn(__fadd_rn(
                s[he][we], -s[hs][we]), -s[he][ws]), s[hs][ws]);
            res = __fdiv_rn(ssum, (float)area);
        }
        out[n * CHN + c] = res;
    }
}

extern "C" void kernel_launch(void* const* d_in, const int* in_sizes, int n_in,
                              void* d_out, int out_size) {
    const float* input = (const float*)d_in[0];   // (4,1029,80,80) f32
    const float* rois  = (const float*)d_in[1];   // (1024,5) f32
    float* out = (float*)d_out;                   // (1024,21,7,7) f32

    psroi_fused_kernel<<<BATCH * CHN, NT>>>(input, rois, out);
}

// round 13
// speedup vs baseline: 1.4697x; 1.4697x over previous
#include <cuda_runtime.h>

#define BATCH 4
#define CHN   1029
#define HH    80
#define WW    80
#define PLANE (HH * WW)
#define NROI  1024
#define PH    7
#define PW    7
#define SCALE 0.0625f
#define SP    81          // padded SAT row stride (odd -> conflict-free LDS)
#define SEG   20          // 4 segments of 20 cover 80
#define NSEG  4
#define NT    320         // 4*80 threads

// Per-batch compacted roi data, rebuilt each launch by psroi_prep.
__device__ int    g_cnt[BATCH];
__device__ float4 g_geo[BATCH][NROI];  // x=roi_sw, y=roi_sh, z=bin_w, w=bin_h
__device__ int    g_idx[BATCH][NROI];  // original roi index n

// ---------------------------------------------------------------------------
// Prep: 8 blocks x 128 threads (parallel across SMs; R11 used 1 block and
// serialized on one SM). Geometry via the validated XLA numerics, compacted
// by batch with global atomics. Slot order is non-deterministic but each
// roi's output location depends only on its own n -> deterministic output.
// ---------------------------------------------------------------------------
__global__ __launch_bounds__(128) void psroi_prep(const float* __restrict__ rois) {
    const int n = blockIdx.x * 128 + threadIdx.x;   // 8*128 = 1024

    const float r0 = rois[n * 5 + 0];
    const float r1 = rois[n * 5 + 1];
    const float r2 = rois[n * 5 + 2];
    const float r3 = rois[n * 5 + 3];
    const float r4 = rois[n * 5 + 4];

    const int b = (int)r0;

    // Validated numerics: rnd = floor(v+0.5), *1/16 exact, *fl(1/7).
    const float roi_sw = __fmul_rn(floorf(__fadd_rn(r1, 0.5f)), SCALE);
    const float roi_sh = __fmul_rn(floorf(__fadd_rn(r2, 0.5f)), SCALE);
    const float roi_ew = __fmul_rn(floorf(__fadd_rn(__fadd_rn(r3, 1.0f), 0.5f)), SCALE);
    const float roi_eh = __fmul_rn(floorf(__fadd_rn(__fadd_rn(r4, 1.0f), 0.5f)), SCALE);

    const float roi_w = fmaxf(__fadd_rn(roi_ew, -roi_sw), 0.1f);
    const float roi_h = fmaxf(__fadd_rn(roi_eh, -roi_sh), 0.1f);

    const float inv7 = 1.0f / 7.0f;   // correctly-rounded (XLA div->recip)
    const float bin_w = __fmul_rn(roi_w, inv7);
    const float bin_h = __fmul_rn(roi_h, inv7);

    const int slot = atomicAdd(&g_cnt[b], 1);
    g_geo[b][slot] = make_float4(roi_sw, roi_sh, bin_w, bin_h);
    g_idx[b][slot] = n;
}

// Zero the counters before prep (tiny, required for graph determinism).
__global__ void psroi_zero() {
    if (threadIdx.x < BATCH) g_cnt[threadIdx.x] = 0;
}

// ---------------------------------------------------------------------------
// Main: one block per (b,c) plane. Segmented register-resident SAT build,
// then pooling over only this batch's rois (coalesced, no divergence):
// 4 SAT LDS + 1 store per bin. 6 blocks/SM (regs fit at 32, smem 168KB).
// ---------------------------------------------------------------------------
__global__ __launch_bounds__(NT, 6) void psroi_sat_seg_kernel(
    const float* __restrict__ in,       // (4,1029,80,80)
    float* __restrict__ out) {          // (1024,21,7,7) == (1024,1029)

    __shared__ float s[SP][SP];         // padded SAT, pad row 0 / col 0
    __shared__ float aux[NSEG][80];     // segment totals (reused by both scans)

    const int tid   = threadIdx.x;
    const int plane = blockIdx.x;       // b*CHN + c
    const int b     = plane / CHN;
    const int c     = plane - b * CHN;

    // zero pad row / pad col
    if (tid < SP) s[0][tid] = 0.0f;
    else if (tid < SP + HH) s[tid - SP + 1][0] = 0.0f;

    const int seg  = tid / 80;          // 0..3
    const int lane = tid - seg * 80;    // 0..79

    // ---- Phase A: H-cumsum, thread = (h-segment, column) ----
    {
        const float* __restrict__ col =
            in + (size_t)plane * PLANE + (size_t)(seg * SEG) * WW + lane;

        float v[SEG];
        #pragma unroll
        for (int i = 0; i < SEG; ++i) v[i] = col[i * WW];   // 20 loads in flight
        #pragma unroll
        for (int i = 1; i < SEG; ++i) v[i] = __fadd_rn(v[i], v[i - 1]);

        aux[seg][lane] = v[SEG - 1];
        __syncthreads();

        float p = 0.0f;
        #pragma unroll
        for (int j = 0; j < NSEG - 1; ++j)
            if (j < seg) p = __fadd_rn(p, aux[j][lane]);

        #pragma unroll
        for (int i = 0; i < SEG; ++i)
            s[seg * SEG + i + 1][lane + 1] = __fadd_rn(v[i], p);
    }
    __syncthreads();

    // ---- Phase B: W-cumsum, thread = (w-segment, row) ----
    {
        float* __restrict__ row = &s[lane + 1][seg * SEG + 1];

        float v[SEG];
        #pragma unroll
        for (int i = 0; i < SEG; ++i) v[i] = row[i];        // independent LDS
        #pragma unroll
        for (int i = 1; i < SEG; ++i) v[i] = __fadd_rn(v[i], v[i - 1]);

        aux[seg][lane] = v[SEG - 1];
        __syncthreads();

        float p = 0.0f;
        #pragma unroll
        for (int j = 0; j < NSEG - 1; ++j)
            if (j < seg) p = __fadd_rn(p, aux[j][lane]);

        #pragma unroll
        for (int i = 0; i < SEG; ++i)
            row[i] = __fadd_rn(v[i], p);
    }
    __syncthreads();

    // ---- Phase C: pooling, fixed (ph, pw); only this batch's rois ----
    const int k  = c % (PH * PW);
    const int ph = k / PW;
    const int pw = k - ph * PW;
    const float fph0 = (float)ph, fph1 = (float)(ph + 1);
    const float fpw0 = (float)pw, fpw1 = (float)(pw + 1);

    const int cnt = g_cnt[b];
    for (int i = tid; i < cnt; i += NT) {
        const float4 gm = g_geo[b][i];   // coalesced 16B
        const int    n  = g_idx[b][i];   // coalesced 4B

        // Uncontracted rn mul+add edges (validated).
        const float hsf = floorf(__fadd_rn(__fmul_rn(fph0, gm.w), gm.y));
        const float hef = ceilf (__fadd_rn(__fmul_rn(fph1, gm.w), gm.y));
        const float wsf = floorf(__fadd_rn(__fmul_rn(fpw0, gm.z), gm.x));
        const float wef = ceilf (__fadd_rn(__fmul_rn(fpw1, gm.z), gm.x));

        const int hs = (int)fminf(fmaxf(hsf, 0.0f), (float)HH);
        const int he = (int)fminf(fmaxf(hef, 0.0f), (float)HH);
        const int ws = (int)fminf(fmaxf(wsf, 0.0f), (float)WW);
        const int we = (int)fminf(fmaxf(wef, 0.0f), (float)WW);

        const int area = (he - hs) * (we - ws);
        float res = 0.0f;
        if (area > 0) {
            const float ssum = __fadd_rn(__fadd_rn(__fadd_rn(
                s[he][we], -s[hs][we]), -s[he][ws]), s[hs][ws]);
            res = __fdiv_rn(ssum, (float)area);
        }
        out[n * CHN + c] = res;
    }
}

extern "C" void kernel_launch(void* const* d_in, const int* in_sizes, int n_in,
                              void* d_out, int out_size) {
    const float* input = (const float*)d_in[0];   // (4,1029,80,80) f32
    const float* rois  = (const float*)d_in[1];   // (1024,5) f32
    float* out = (float*)d_out;                   // (1024,21,7,7) f32

    psroi_zero<<<1, 32>>>();
    psroi_prep<<<8, 128>>>(rois);
    psroi_sat_seg_kernel<<<BATCH * CHN, NT>>>(input, out);
}

// round 14
// speedup vs baseline: 1.5645x; 1.0645x over previous
#include <cuda_runtime.h>

#define BATCH 4
#define CHN   1029
#define HH    80
#define WW    80
#define PLANE (HH * WW)
#define NROI  1024
#define PH    7
#define PW    7
#define SCALE 0.0625f
#define SP    81          // padded SAT row stride (odd -> conflict-free LDS)
#define SEG   20          // 4 segments of 20 cover 80
#define NSEG  4
#define NT    320         // 4*80 threads

// Per-batch compacted roi data, rebuilt every launch by psroi_prep.
__device__ int    g_cnt[BATCH];
__device__ float4 g_geo[BATCH][NROI];  // x=roi_sw, y=roi_sh, z=bin_w, w=bin_h
__device__ int    g_idx[BATCH][NROI];  // original roi index n

// ---------------------------------------------------------------------------
// Prep: ONE block, 1024 threads. Compaction via shared-memory counters
// (fast ATOMS; no pre-zeroing kernel needed — counters live in smem and
// g_cnt is written fresh at the end of every launch -> replay-safe).
// Slot order is non-deterministic but each roi's output location depends
// only on its own n, so the final output is deterministic.
// ---------------------------------------------------------------------------
__global__ __launch_bounds__(NROI) void psroi_prep(const float* __restrict__ rois) {
    __shared__ int scnt[BATCH];
    const int n = threadIdx.x;
    if (n < BATCH) scnt[n] = 0;
    __syncthreads();

    const float r0 = rois[n * 5 + 0];
    const float r1 = rois[n * 5 + 1];
    const float r2 = rois[n * 5 + 2];
    const float r3 = rois[n * 5 + 3];
    const float r4 = rois[n * 5 + 4];

    const int b = (int)r0;

    // Validated numerics: rnd = floor(v+0.5), *1/16 exact, *fl(1/7).
    const float roi_sw = __fmul_rn(floorf(__fadd_rn(r1, 0.5f)), SCALE);
    const float roi_sh = __fmul_rn(floorf(__fadd_rn(r2, 0.5f)), SCALE);
    const float roi_ew = __fmul_rn(floorf(__fadd_rn(__fadd_rn(r3, 1.0f), 0.5f)), SCALE);
    const float roi_eh = __fmul_rn(floorf(__fadd_rn(__fadd_rn(r4, 1.0f), 0.5f)), SCALE);

    const float roi_w = fmaxf(__fadd_rn(roi_ew, -roi_sw), 0.1f);
    const float roi_h = fmaxf(__fadd_rn(roi_eh, -roi_sh), 0.1f);

    const float inv7 = 1.0f / 7.0f;   // correctly-rounded (XLA div->recip)
    const float bin_w = __fmul_rn(roi_w, inv7);
    const float bin_h = __fmul_rn(roi_h, inv7);

    const int slot = atomicAdd(&scnt[b], 1);   // smem atomic: cheap
    g_geo[b][slot] = make_float4(roi_sw, roi_sh, bin_w, bin_h);
    g_idx[b][slot] = n;

    __syncthreads();
    if (n < BATCH) g_cnt[n] = scnt[n];
}

// ---------------------------------------------------------------------------
// Main: one block per (b,c) plane. Segmented register-resident SAT build,
// then pooling over only this batch's rois (coalesced, no divergence):
// 4 SAT LDS + 1 store per bin. 6 blocks/SM (regs fit at 32, smem 168KB).
// ---------------------------------------------------------------------------
__global__ __launch_bounds__(NT, 6) void psroi_sat_seg_kernel(
    const float* __restrict__ in,       // (4,1029,80,80)
    float* __restrict__ out) {          // (1024,21,7,7) == (1024,1029)

    __shared__ float s[SP][SP];         // padded SAT, pad row 0 / col 0
    __shared__ float aux[NSEG][80];     // segment totals (reused by both scans)

    const int tid   = threadIdx.x;
    const int plane = blockIdx.x;       // b*CHN + c
    const int b     = plane / CHN;
    const int c     = plane - b * CHN;

    // zero pad row / pad col
    if (tid < SP) s[0][tid] = 0.0f;
    else if (tid < SP + HH) s[tid - SP + 1][0] = 0.0f;

    const int seg  = tid / 80;          // 0..3
    const int lane = tid - seg * 80;    // 0..79

    // ---- Phase A: H-cumsum, thread = (h-segment, column) ----
    {
        const float* __restrict__ col =
            in + (size_t)plane * PLANE + (size_t)(seg * SEG) * WW + lane;

        float v[SEG];
        #pragma unroll
        for (int i = 0; i < SEG; ++i) v[i] = col[i * WW];   // 20 loads in flight
        #pragma unroll
        for (int i = 1; i < SEG; ++i) v[i] = __fadd_rn(v[i], v[i - 1]);

        aux[seg][lane] = v[SEG - 1];
        __syncthreads();

        float p = 0.0f;
        #pragma unroll
        for (int j = 0; j < NSEG - 1; ++j)
            if (j < seg) p = __fadd_rn(p, aux[j][lane]);

        #pragma unroll
        for (int i = 0; i < SEG; ++i)
            s[seg * SEG + i + 1][lane + 1] = __fadd_rn(v[i], p);
    }
    __syncthreads();

    // ---- Phase B: W-cumsum, thread = (w-segment, row) ----
    {
        float* __restrict__ row = &s[lane + 1][seg * SEG + 1];

        float v[SEG];
        #pragma unroll
        for (int i = 0; i < SEG; ++i) v[i] = row[i];        // independent LDS
        #pragma unroll
        for (int i = 1; i < SEG; ++i) v[i] = __fadd_rn(v[i], v[i - 1]);

        aux[seg][lane] = v[SEG - 1];
        __syncthreads();

        float p = 0.0f;
        #pragma unroll
        for (int j = 0; j < NSEG - 1; ++j)
            if (j < seg) p = __fadd_rn(p, aux[j][lane]);

        #pragma unroll
        for (int i = 0; i < SEG; ++i)
            row[i] = __fadd_rn(v[i], p);
    }
    __syncthreads();

    // ---- Phase C: pooling, fixed (ph, pw); only this batch's rois ----
    const int k  = c % (PH * PW);
    const int ph = k / PW;
    const int pw = k - ph * PW;
    const float fph0 = (float)ph, fph1 = (float)(ph + 1);
    const float fpw0 = (float)pw, fpw1 = (float)(pw + 1);

    const int cnt = g_cnt[b];
    for (int i = tid; i < cnt; i += NT) {
        const float4 gm = g_geo[b][i];   // coalesced 16B
        const int    n  = g_idx[b][i];   // coalesced 4B

        // Uncontracted rn mul+add edges (validated).
        const float hsf = floorf(__fadd_rn(__fmul_rn(fph0, gm.w), gm.y));
        const float hef = ceilf (__fadd_rn(__fmul_rn(fph1, gm.w), gm.y));
        const float wsf = floorf(__fadd_rn(__fmul_rn(fpw0, gm.z), gm.x));
        const float wef = ceilf (__fadd_rn(__fmul_rn(fpw1, gm.z), gm.x));

        const int hs = (int)fminf(fmaxf(hsf, 0.0f), (float)HH);
        const int he = (int)fminf(fmaxf(hef, 0.0f), (float)HH);
        const int ws = (int)fminf(fmaxf(wsf, 0.0f), (float)WW);
        const int we = (int)fminf(fmaxf(wef, 0.0f), (float)WW);

        const int area = (he - hs) * (we - ws);
        float res = 0.0f;
        if (area > 0) {
            const float ssum = __fadd_rn(__fadd_rn(__fadd_rn(
                s[he][we], -s[hs][we]), -s[he][ws]), s[hs][ws]);
            res = __fdiv_rn(ssum, (float)area);
        }
        out[n * CHN + c] = res;
    }
}

extern "C" void kernel_launch(void* const* d_in, const int* in_sizes, int n_in,
                              void* d_out, int out_size) {
    const float* input = (const float*)d_in[0];   // (4,1029,80,80) f32
    const float* rois  = (const float*)d_in[1];   // (1024,5) f32
    float* out = (float*)d_out;                   // (1024,21,7,7) f32

    psroi_prep<<<1, NROI>>>(rois);
    psroi_sat_seg_kernel<<<BATCH * CHN, NT>>>(input, out);
}